// round 3
// baseline (speedup 1.0000x reference)
#include <cuda_runtime.h>
#include <cuda_bf16.h>
#include <math_constants.h>
#include <cstdint>

#define N_TOK 4096
#define DIM   1024

// ---------------- scratch (__device__ globals; allocation-free contract) ----
__device__ float g_Q[(size_t)N_TOK * DIM];
__device__ float g_K[(size_t)N_TOK * DIM];
__device__ float g_S[(size_t)N_TOK * N_TOK];
__device__ __nv_bfloat16 g_Xs [(size_t)N_TOK * 3 * DIM];   // split3 of X    [4096, 3072]
__device__ __nv_bfloat16 g_Wqt[(size_t)DIM   * 3 * DIM];   // split3 of Wq^T [1024, 3072]
__device__ __nv_bfloat16 g_Wkt[(size_t)DIM   * 3 * DIM];   // split3 of Wk^T [1024, 3072]
__device__ __nv_bfloat16 g_Qs [(size_t)N_TOK * 3 * DIM];   // split3 of Q    [4096, 3072]
__device__ __nv_bfloat16 g_Ks [(size_t)N_TOK * 3 * DIM];   // split3 of K    [4096, 3072]
__device__ __nv_bfloat16 g_Ss [(size_t)N_TOK * 2 * N_TOK]; // split2 of S    [4096, 8192]
__device__ __nv_bfloat16 g_Xt [(size_t)DIM   * 2 * N_TOK]; // split2 of X^T  [1024, 8192]

// ---------------------------------------------------------------------------
// HMMA split-bf16 GEMM:  C[M,N] = alpha * sum_pairs A_split[sa] @ B_split[sb]^T
// A: [M, SPLITS*K] bf16 row-major.  B: [N, SPLITS*K] bf16 row-major (K-major).
// Block 128x128, BK=32, 8 warps (2x4), warp tile 64x32, mma.m16n8k16.
// smem rows: 32 bf16 (64B) padded to 80B stride -> conflict-free ldmatrix.
// ---------------------------------------------------------------------------
#define ROW_B 80
#define TILE_BYTES (128 * ROW_B)            // 10240 per operand
#define STAGE_BYTES (2 * TILE_BYTES)        // 20480
#define STAGES 4
#define GEMM_SMEM (STAGES * STAGE_BYTES)    // 81920

__device__ __forceinline__ uint32_t smem_u32(const void* p) {
    uint32_t a;
    asm("{ .reg .u64 t; cvta.to.shared.u64 t, %1; cvt.u32.u64 %0, t; }" : "=r"(a) : "l"(p));
    return a;
}
__device__ __forceinline__ void cp16(uint32_t dst, const void* src) {
    asm volatile("cp.async.cg.shared.global [%0], [%1], 16;\n" :: "r"(dst), "l"(src));
}
__device__ __forceinline__ void ldm_x4(uint32_t* r, uint32_t addr) {
    asm volatile("ldmatrix.sync.aligned.m8n8.x4.shared.b16 {%0,%1,%2,%3}, [%4];"
                 : "=r"(r[0]), "=r"(r[1]), "=r"(r[2]), "=r"(r[3]) : "r"(addr));
}
__device__ __forceinline__ void mma16816(float* c, const uint32_t* a, const uint32_t* b) {
    asm volatile("mma.sync.aligned.m16n8k16.row.col.f32.bf16.bf16.f32 "
                 "{%0,%1,%2,%3}, {%4,%5,%6,%7}, {%8,%9}, {%0,%1,%2,%3};"
                 : "+f"(c[0]), "+f"(c[1]), "+f"(c[2]), "+f"(c[3])
                 : "r"(a[0]), "r"(a[1]), "r"(a[2]), "r"(a[3]), "r"(b[0]), "r"(b[1]));
}

template <int NPAIRS, int SPLITS>
__global__ __launch_bounds__(256, 2)
void gemm_split(const __nv_bfloat16* __restrict__ A, const __nv_bfloat16* __restrict__ B,
                float* __restrict__ C, int N, int K, int kchunks, float alpha)
{
    extern __shared__ char smem[];
    const uint32_t su = smem_u32(smem);
    const int tid = threadIdx.x;
    const int wid = tid >> 5;
    const int lane = tid & 31;
    const int warp_m = wid >> 2;      // 0..1
    const int warp_n = wid & 3;       // 0..3
    const int lda = SPLITS * K;

    // 2-split/3-product list is a prefix of the 3-split/6-product list
    const int ta[6] = {0, 0, 1, 0, 2, 1};
    const int tb[6] = {0, 1, 0, 2, 0, 1};

    const int nch = NPAIRS * kchunks;

    float acc[4][4][4];
#pragma unroll
    for (int i = 0; i < 4; i++)
#pragma unroll
        for (int j = 0; j < 4; j++)
#pragma unroll
            for (int t = 0; t < 4; t++) acc[i][j][t] = 0.0f;

    auto load_chunk = [&](int cc) {
        int p  = cc / kchunks;
        int kc = cc - p * kchunks;
        const __nv_bfloat16* aB = A + (size_t)(blockIdx.y * 128) * lda + (size_t)ta[p] * K + kc * 32;
        const __nv_bfloat16* bB = B + (size_t)(blockIdx.x * 128) * lda + (size_t)tb[p] * K + kc * 32;
        uint32_t sA = su + (cc & (STAGES - 1)) * STAGE_BYTES;
        uint32_t sB = sA + TILE_BYTES;
#pragma unroll
        for (int i = 0; i < 2; i++) {
            int s = tid + i * 256, row = s >> 2, seg = s & 3;
            cp16(sA + row * ROW_B + seg * 16, aB + (size_t)row * lda + seg * 8);
        }
#pragma unroll
        for (int i = 0; i < 2; i++) {
            int s = tid + i * 256, row = s >> 2, seg = s & 3;
            cp16(sB + row * ROW_B + seg * 16, bB + (size_t)row * lda + seg * 8);
        }
        asm volatile("cp.async.commit_group;\n" ::: "memory");
    };

    // prologue: stages 0..2
#pragma unroll
    for (int c = 0; c < STAGES - 1; c++)
        if (c < nch) load_chunk(c);
        else asm volatile("cp.async.commit_group;\n" ::: "memory");

    // precomputed intra-tile ldmatrix offsets
    const uint32_t a_off = (uint32_t)((warp_m * 64 + (lane & 15)) * ROW_B + ((lane >> 4) * 8) * 2);
    const uint32_t b_off = (uint32_t)((warp_n * 32 + (lane & 7) + ((lane >> 4) & 1) * 8) * ROW_B
                                      + (((lane >> 3) & 1) * 8) * 2);

    for (int c = 0; c < nch; c++) {
        asm volatile("cp.async.wait_group %0;\n" :: "n"(STAGES - 2) : "memory");
        __syncthreads();

        uint32_t sA = su + (c & (STAGES - 1)) * STAGE_BYTES;
        uint32_t sB = sA + TILE_BYTES;
#pragma unroll
        for (int p = 0; p < 2; p++) {
            uint32_t a[4][4], b[2][4];
#pragma unroll
            for (int mt = 0; mt < 4; mt++)
                ldm_x4(a[mt], sA + a_off + mt * 16 * ROW_B + p * 32);
#pragma unroll
            for (int np = 0; np < 2; np++)
                ldm_x4(b[np], sB + b_off + np * 16 * ROW_B + p * 32);
#pragma unroll
            for (int mt = 0; mt < 4; mt++)
#pragma unroll
                for (int nt = 0; nt < 4; nt++)
                    mma16816(acc[mt][nt], a[mt], &b[nt >> 1][(nt & 1) * 2]);
        }
        __syncthreads();

        int cl = c + STAGES - 1;
        if (cl < nch) load_chunk(cl);
        else asm volatile("cp.async.commit_group;\n" ::: "memory");
    }

    // epilogue: direct fp32 stores
    const int row0 = blockIdx.y * 128 + warp_m * 64 + (lane >> 2);
    const int col0 = blockIdx.x * 128 + warp_n * 32 + (lane & 3) * 2;
#pragma unroll
    for (int mt = 0; mt < 4; mt++) {
#pragma unroll
        for (int nt = 0; nt < 4; nt++) {
            float2 v0 = make_float2(alpha * acc[mt][nt][0], alpha * acc[mt][nt][1]);
            float2 v1 = make_float2(alpha * acc[mt][nt][2], alpha * acc[mt][nt][3]);
            size_t r0 = (size_t)(row0 + mt * 16) * N + col0 + nt * 8;
            *reinterpret_cast<float2*>(&C[r0])               = v0;
            *reinterpret_cast<float2*>(&C[r0 + (size_t)8 * N]) = v1;
        }
    }
}

// ---------------------------------------------------------------------------
// Split kernels
// ---------------------------------------------------------------------------
template <int S>
__global__ __launch_bounds__(256)
void split_rows(const float* __restrict__ in, __nv_bfloat16* __restrict__ out, int C)
{
    size_t idx = (size_t)blockIdx.x * blockDim.x + threadIdx.x;   // one float4
    int cq = C >> 2;
    size_t r = idx / cq;
    int c4 = (int)(idx - r * cq);
    float4 v = reinterpret_cast<const float4*>(in)[idx];
    float x[4] = {v.x, v.y, v.z, v.w};
    __nv_bfloat16 h[S][4];
#pragma unroll
    for (int i = 0; i < 4; i++) {
        float rem = x[i];
#pragma unroll
        for (int s = 0; s < S; s++) {
            __nv_bfloat16 b = __float2bfloat16_rn(rem);
            h[s][i] = b;
            rem -= __bfloat162float(b);
        }
    }
    __nv_bfloat16* o = out + r * ((size_t)S * C) + c4 * 4;
#pragma unroll
    for (int s = 0; s < S; s++) {
        __nv_bfloat162 p0, p1;
        p0.x = h[s][0]; p0.y = h[s][1]; p1.x = h[s][2]; p1.y = h[s][3];
        *reinterpret_cast<__nv_bfloat162*>(o + (size_t)s * C)     = p0;
        *reinterpret_cast<__nv_bfloat162*>(o + (size_t)s * C + 2) = p1;
    }
}

// in [K,N] fp32 -> out [N, S*K] bf16 (transpose + split)
template <int S>
__global__ __launch_bounds__(256)
void splitT(const float* __restrict__ in, __nv_bfloat16* __restrict__ out, int K, int N)
{
    __shared__ float tile[32][33];
    int k0 = blockIdx.y * 32, n0 = blockIdx.x * 32;
    int tx = threadIdx.x, ty = threadIdx.y;   // (32, 8)
#pragma unroll
    for (int j = 0; j < 4; j++)
        tile[ty + j * 8][tx] = in[(size_t)(k0 + ty + j * 8) * N + n0 + tx];
    __syncthreads();
#pragma unroll
    for (int j = 0; j < 4; j++) {
        int n = n0 + ty + j * 8, k = k0 + tx;
        float rem = tile[tx][ty + j * 8];
        __nv_bfloat16* o = out + (size_t)n * (S * K) + k;
#pragma unroll
        for (int s = 0; s < S; s++) {
            __nv_bfloat16 b = __float2bfloat16_rn(rem);
            rem -= __bfloat162float(b);
            o[(size_t)s * K] = b;
        }
    }
}

// ---------------------------------------------------------------------------
// Row softmax
// ---------------------------------------------------------------------------
__global__ __launch_bounds__(256)
void softmax_rows(float* __restrict__ S)
{
    const int row = blockIdx.x;
    float* r = S + (size_t)row * N_TOK;
    const int tid = threadIdx.x;

    float v[16];
    float m = -CUDART_INF_F;
#pragma unroll
    for (int i = 0; i < 16; i++) { v[i] = r[tid + i * 256]; m = fmaxf(m, v[i]); }

    __shared__ float red[8];
#pragma unroll
    for (int o = 16; o > 0; o >>= 1) m = fmaxf(m, __shfl_xor_sync(0xffffffffu, m, o));
    if ((tid & 31) == 0) red[tid >> 5] = m;
    __syncthreads();
    m = red[0];
#pragma unroll
    for (int w = 1; w < 8; w++) m = fmaxf(m, red[w]);

    float sum = 0.0f;
#pragma unroll
    for (int i = 0; i < 16; i++) { v[i] = expf(v[i] - m); sum += v[i]; }
    __syncthreads();
#pragma unroll
    for (int o = 16; o > 0; o >>= 1) sum += __shfl_xor_sync(0xffffffffu, sum, o);
    if ((tid & 31) == 0) red[tid >> 5] = sum;
    __syncthreads();
    sum = 0.0f;
#pragma unroll
    for (int w = 0; w < 8; w++) sum += red[w];

    const float inv = 1.0f / sum;
#pragma unroll
    for (int i = 0; i < 16; i++) r[tid + i * 256] = v[i] * inv;
}

// ---------------------------------------------------------------------------
extern "C" void kernel_launch(void* const* d_in, const int* in_sizes, int n_in,
                              void* d_out, int out_size)
{
    const float* X  = (const float*)d_in[0];
    const float* Wq = (const float*)d_in[1];
    const float* Wk = (const float*)d_in[2];
    float* O = (float*)d_out;

    float *Q, *K, *S;
    __nv_bfloat16 *Xs, *Wqt, *Wkt, *Qs, *Ks, *Ss, *Xt;
    cudaGetSymbolAddress((void**)&Q,  g_Q);
    cudaGetSymbolAddress((void**)&K,  g_K);
    cudaGetSymbolAddress((void**)&S,  g_S);
    cudaGetSymbolAddress((void**)&Xs, g_Xs);
    cudaGetSymbolAddress((void**)&Wqt, g_Wqt);
    cudaGetSymbolAddress((void**)&Wkt, g_Wkt);
    cudaGetSymbolAddress((void**)&Qs, g_Qs);
    cudaGetSymbolAddress((void**)&Ks, g_Ks);
    cudaGetSymbolAddress((void**)&Ss, g_Ss);
    cudaGetSymbolAddress((void**)&Xt, g_Xt);

    cudaFuncSetAttribute(gemm_split<6, 3>, cudaFuncAttributeMaxDynamicSharedMemorySize, GEMM_SMEM);
    cudaFuncSetAttribute(gemm_split<3, 2>, cudaFuncAttributeMaxDynamicSharedMemorySize, GEMM_SMEM);

    // split inputs
    split_rows<3><<<(N_TOK * DIM / 4) / 256, 256>>>(X, Xs, DIM);
    splitT<3><<<dim3(DIM / 32, DIM / 32), dim3(32, 8)>>>(Wq, Wqt, DIM, DIM);
    splitT<3><<<dim3(DIM / 32, DIM / 32), dim3(32, 8)>>>(Wk, Wkt, DIM, DIM);

    // Q = X Wq ; K = X Wk   (M=4096, N=1024, K=1024)
    gemm_split<6, 3><<<dim3(DIM / 128, N_TOK / 128), 256, GEMM_SMEM>>>(Xs, Wqt, Q, DIM, DIM, DIM / 32, 1.0f);
    gemm_split<6, 3><<<dim3(DIM / 128, N_TOK / 128), 256, GEMM_SMEM>>>(Xs, Wkt, K, DIM, DIM, DIM / 32, 1.0f);

    // split Q, K
    split_rows<3><<<(N_TOK * DIM / 4) / 256, 256>>>(Q, Qs, DIM);
    split_rows<3><<<(N_TOK * DIM / 4) / 256, 256>>>(K, Ks, DIM);

    // S = (Q K^T) / 32   (M=N=4096, K=1024)
    gemm_split<6, 3><<<dim3(N_TOK / 128, N_TOK / 128), 256, GEMM_SMEM>>>(Qs, Ks, S, N_TOK, DIM, DIM / 32, 0.03125f);

    softmax_rows<<<N_TOK, 256>>>(S);

    // split S (2-way) and X^T (2-way)
    split_rows<2><<<((size_t)N_TOK * N_TOK / 4) / 256, 256>>>(S, Ss, N_TOK);
    splitT<2><<<dim3(DIM / 32, N_TOK / 32), dim3(32, 8)>>>(X, Xt, N_TOK, DIM);

    // O = S X   (M=4096, N=1024, K=4096)
    gemm_split<3, 2><<<dim3(DIM / 128, N_TOK / 128), 256, GEMM_SMEM>>>(Ss, Xt, O, DIM, N_TOK, N_TOK / 32, 1.0f);
}

// round 4
// speedup vs baseline: 2.2498x; 2.2498x over previous
#include <cuda_runtime.h>
#include <cuda_bf16.h>
#include <math_constants.h>
#include <cstdint>

#define N_TOK 4096
#define DIM   1024

// ---------------- scratch (__device__ globals; allocation-free contract) ----
__device__ float g_Q[(size_t)N_TOK * DIM];
__device__ float g_K[(size_t)N_TOK * DIM];
__device__ float g_S[(size_t)N_TOK * N_TOK];
__device__ __nv_bfloat16 g_Xs [(size_t)N_TOK * 3 * DIM];   // split3 of X    [4096, 3072]
__device__ __nv_bfloat16 g_Wqt[(size_t)DIM   * 3 * DIM];   // split3 of Wq^T [1024, 3072]
__device__ __nv_bfloat16 g_Wkt[(size_t)DIM   * 3 * DIM];   // split3 of Wk^T [1024, 3072]
__device__ __nv_bfloat16 g_Qs [(size_t)N_TOK * 3 * DIM];   // split3 of Q    [4096, 3072]
__device__ __nv_bfloat16 g_Ks [(size_t)N_TOK * 3 * DIM];   // split3 of K    [4096, 3072]
__device__ __nv_bfloat16 g_Ss [(size_t)N_TOK * 2 * N_TOK]; // split2 of S    [4096, 8192]
__device__ __nv_bfloat16 g_Xt [(size_t)DIM   * 2 * N_TOK]; // split2 of X^T  [1024, 8192]

// ---------------------------------------------------------------------------
// HMMA split-bf16 GEMM:  C[M,N] = alpha * sum_pairs A_split[sa] @ B_split[sb]^T
// A: [M, SPLITS*K] bf16 row-major.  B: [N, SPLITS*K] bf16 row-major (K-major).
// Block 128x128, BK=64, 8 warps (2x4), warp tile 64x32, mma.m16n8k16.
// smem rows: 64 bf16 (128B) padded to 144B stride -> conflict-free ldmatrix
// (bank starts per 8-row group: {0,4,8,...,28}*4B, disjoint 4-bank spans).
// 3 stages, ONE __syncthreads per chunk: slot (c+S-1)%S == (c-1)%S whose
// compute finished before this iteration's barrier.
// ---------------------------------------------------------------------------
#define ROW_B 144
#define TILE_BYTES (128 * ROW_B)            // 18432 per operand
#define STAGE_BYTES (2 * TILE_BYTES)        // 36864
#define STAGES 3
#define GEMM_SMEM (STAGES * STAGE_BYTES)    // 110592

__device__ __forceinline__ uint32_t smem_u32(const void* p) {
    uint32_t a;
    asm("{ .reg .u64 t; cvta.to.shared.u64 t, %1; cvt.u32.u64 %0, t; }" : "=r"(a) : "l"(p));
    return a;
}
__device__ __forceinline__ void cp16(uint32_t dst, const void* src) {
    asm volatile("cp.async.cg.shared.global [%0], [%1], 16;\n" :: "r"(dst), "l"(src));
}
__device__ __forceinline__ void ldm_x4(uint32_t* r, uint32_t addr) {
    asm volatile("ldmatrix.sync.aligned.m8n8.x4.shared.b16 {%0,%1,%2,%3}, [%4];"
                 : "=r"(r[0]), "=r"(r[1]), "=r"(r[2]), "=r"(r[3]) : "r"(addr));
}
__device__ __forceinline__ void mma16816(float* c, const uint32_t* a, const uint32_t* b) {
    asm volatile("mma.sync.aligned.m16n8k16.row.col.f32.bf16.bf16.f32 "
                 "{%0,%1,%2,%3}, {%4,%5,%6,%7}, {%8,%9}, {%0,%1,%2,%3};"
                 : "+f"(c[0]), "+f"(c[1]), "+f"(c[2]), "+f"(c[3])
                 : "r"(a[0]), "r"(a[1]), "r"(a[2]), "r"(a[3]), "r"(b[0]), "r"(b[1]));
}

template <int NPAIRS, int SPLITS>
__global__ __launch_bounds__(256, 2)
void gemm_split(const __nv_bfloat16* __restrict__ A, const __nv_bfloat16* __restrict__ B,
                float* __restrict__ C, int N, int K, int kchunks, float alpha)
{
    extern __shared__ char smem[];
    const uint32_t su = smem_u32(smem);
    const int tid = threadIdx.x;
    const int wid = tid >> 5;
    const int lane = tid & 31;
    const int warp_m = wid >> 2;      // 0..1
    const int warp_n = wid & 3;       // 0..3
    const int lda = SPLITS * K;

    // product order: hh, hm, mh, mm, hl, lh
    //   NPAIRS=3 (2-split): hh, hm, mh
    //   NPAIRS=4 (3-split fast logits): hh, hm, mh, mm
    //   NPAIRS=6 (3-split full): + hl, lh
    const int ta[6] = {0, 0, 1, 1, 0, 2};
    const int tb[6] = {0, 1, 0, 1, 2, 0};

    const int nch = NPAIRS * kchunks;

    float acc[4][4][4];
#pragma unroll
    for (int i = 0; i < 4; i++)
#pragma unroll
        for (int j = 0; j < 4; j++)
#pragma unroll
            for (int t = 0; t < 4; t++) acc[i][j][t] = 0.0f;

    auto load_chunk = [&](int cc) {
        int p  = cc / kchunks;
        int kc = cc - p * kchunks;
        const __nv_bfloat16* aB = A + (size_t)(blockIdx.y * 128) * lda + (size_t)ta[p] * K + kc * 64;
        const __nv_bfloat16* bB = B + (size_t)(blockIdx.x * 128) * lda + (size_t)tb[p] * K + kc * 64;
        uint32_t sA = su + (cc % STAGES) * STAGE_BYTES;
        uint32_t sB = sA + TILE_BYTES;
#pragma unroll
        for (int i = 0; i < 4; i++) {
            int s = tid + i * 256, row = s >> 3, seg = s & 7;
            cp16(sA + row * ROW_B + seg * 16, aB + (size_t)row * lda + seg * 8);
        }
#pragma unroll
        for (int i = 0; i < 4; i++) {
            int s = tid + i * 256, row = s >> 3, seg = s & 7;
            cp16(sB + row * ROW_B + seg * 16, bB + (size_t)row * lda + seg * 8);
        }
        asm volatile("cp.async.commit_group;\n" ::: "memory");
    };

    // prologue: stages 0..1
#pragma unroll
    for (int c = 0; c < STAGES - 1; c++)
        if (c < nch) load_chunk(c);

    // intra-tile ldmatrix offsets
    const uint32_t a_off = (uint32_t)((warp_m * 64 + (lane & 15)) * ROW_B + (lane >> 4) * 16);
    const uint32_t b_off = (uint32_t)((warp_n * 32 + (lane & 7) + ((lane >> 4) & 1) * 8) * ROW_B
                                      + ((lane >> 3) & 1) * 16);

    for (int c = 0; c < nch; c++) {
        asm volatile("cp.async.wait_group %0;\n" :: "n"(STAGES - 2) : "memory");
        __syncthreads();

        uint32_t sA = su + (c % STAGES) * STAGE_BYTES;
        uint32_t sB = sA + TILE_BYTES;
#pragma unroll
        for (int p = 0; p < 4; p++) {
            uint32_t a[4][4], b[2][4];
#pragma unroll
            for (int mt = 0; mt < 4; mt++)
                ldm_x4(a[mt], sA + a_off + mt * 16 * ROW_B + p * 32);
#pragma unroll
            for (int np = 0; np < 2; np++)
                ldm_x4(b[np], sB + b_off + np * 16 * ROW_B + p * 32);
#pragma unroll
            for (int mt = 0; mt < 4; mt++)
#pragma unroll
                for (int nt = 0; nt < 4; nt++)
                    mma16816(acc[mt][nt], a[mt], &b[nt >> 1][(nt & 1) * 2]);
        }

        int cl = c + STAGES - 1;
        if (cl < nch) load_chunk(cl);   // reuses slot (c-1)%S: compute done before this barrier
    }

    // epilogue: direct fp32 stores
    const int row0 = blockIdx.y * 128 + warp_m * 64 + (lane >> 2);
    const int col0 = blockIdx.x * 128 + warp_n * 32 + (lane & 3) * 2;
#pragma unroll
    for (int mt = 0; mt < 4; mt++) {
#pragma unroll
        for (int nt = 0; nt < 4; nt++) {
            float2 v0 = make_float2(alpha * acc[mt][nt][0], alpha * acc[mt][nt][1]);
            float2 v1 = make_float2(alpha * acc[mt][nt][2], alpha * acc[mt][nt][3]);
            size_t r0 = (size_t)(row0 + mt * 16) * N + col0 + nt * 8;
            *reinterpret_cast<float2*>(&C[r0])                 = v0;
            *reinterpret_cast<float2*>(&C[r0 + (size_t)8 * N]) = v1;
        }
    }
}

// ---------------------------------------------------------------------------
// Split kernels
// ---------------------------------------------------------------------------
template <int S>
__global__ __launch_bounds__(256)
void split_rows(const float* __restrict__ in, __nv_bfloat16* __restrict__ out, int C)
{
    size_t idx = (size_t)blockIdx.x * blockDim.x + threadIdx.x;   // one float4
    int cq = C >> 2;
    size_t r = idx / cq;
    int c4 = (int)(idx - r * cq);
    float4 v = reinterpret_cast<const float4*>(in)[idx];
    float x[4] = {v.x, v.y, v.z, v.w};
    __nv_bfloat16 h[S][4];
#pragma unroll
    for (int i = 0; i < 4; i++) {
        float rem = x[i];
#pragma unroll
        for (int s = 0; s < S; s++) {
            __nv_bfloat16 b = __float2bfloat16_rn(rem);
            h[s][i] = b;
            rem -= __bfloat162float(b);
        }
    }
    __nv_bfloat16* o = out + r * ((size_t)S * C) + c4 * 4;
#pragma unroll
    for (int s = 0; s < S; s++) {
        __nv_bfloat162 p0, p1;
        p0.x = h[s][0]; p0.y = h[s][1]; p1.x = h[s][2]; p1.y = h[s][3];
        *reinterpret_cast<__nv_bfloat162*>(o + (size_t)s * C)     = p0;
        *reinterpret_cast<__nv_bfloat162*>(o + (size_t)s * C + 2) = p1;
    }
}

// in [K,N] fp32 -> out [N, S*K] bf16 (transpose + split)
template <int S>
__global__ __launch_bounds__(256)
void splitT(const float* __restrict__ in, __nv_bfloat16* __restrict__ out, int K, int N)
{
    __shared__ float tile[32][33];
    int k0 = blockIdx.y * 32, n0 = blockIdx.x * 32;
    int tx = threadIdx.x, ty = threadIdx.y;   // (32, 8)
#pragma unroll
    for (int j = 0; j < 4; j++)
        tile[ty + j * 8][tx] = in[(size_t)(k0 + ty + j * 8) * N + n0 + tx];
    __syncthreads();
#pragma unroll
    for (int j = 0; j < 4; j++) {
        int n = n0 + ty + j * 8, k = k0 + tx;
        float rem = tile[tx][ty + j * 8];
        __nv_bfloat16* o = out + (size_t)n * (S * K) + k;
#pragma unroll
        for (int s = 0; s < S; s++) {
            __nv_bfloat16 b = __float2bfloat16_rn(rem);
            rem -= __bfloat162float(b);
            o[(size_t)s * K] = b;
        }
    }
}

// ---------------------------------------------------------------------------
// Row softmax
// ---------------------------------------------------------------------------
__global__ __launch_bounds__(256)
void softmax_rows(float* __restrict__ S)
{
    const int row = blockIdx.x;
    float* r = S + (size_t)row * N_TOK;
    const int tid = threadIdx.x;

    float v[16];
    float m = -CUDART_INF_F;
#pragma unroll
    for (int i = 0; i < 16; i++) { v[i] = r[tid + i * 256]; m = fmaxf(m, v[i]); }

    __shared__ float red[8];
#pragma unroll
    for (int o = 16; o > 0; o >>= 1) m = fmaxf(m, __shfl_xor_sync(0xffffffffu, m, o));
    if ((tid & 31) == 0) red[tid >> 5] = m;
    __syncthreads();
    m = red[0];
#pragma unroll
    for (int w = 1; w < 8; w++) m = fmaxf(m, red[w]);

    float sum = 0.0f;
#pragma unroll
    for (int i = 0; i < 16; i++) { v[i] = expf(v[i] - m); sum += v[i]; }
    __syncthreads();
#pragma unroll
    for (int o = 16; o > 0; o >>= 1) sum += __shfl_xor_sync(0xffffffffu, sum, o);
    if ((tid & 31) == 0) red[tid >> 5] = sum;
    __syncthreads();
    sum = 0.0f;
#pragma unroll
    for (int w = 0; w < 8; w++) sum += red[w];

    const float inv = 1.0f / sum;
#pragma unroll
    for (int i = 0; i < 16; i++) r[tid + i * 256] = v[i] * inv;
}

// ---------------------------------------------------------------------------
extern "C" void kernel_launch(void* const* d_in, const int* in_sizes, int n_in,
                              void* d_out, int out_size)
{
    const float* X  = (const float*)d_in[0];
    const float* Wq = (const float*)d_in[1];
    const float* Wk = (const float*)d_in[2];
    float* O = (float*)d_out;

    float *Q, *K, *S;
    __nv_bfloat16 *Xs, *Wqt, *Wkt, *Qs, *Ks, *Ss, *Xt;
    cudaGetSymbolAddress((void**)&Q,  g_Q);
    cudaGetSymbolAddress((void**)&K,  g_K);
    cudaGetSymbolAddress((void**)&S,  g_S);
    cudaGetSymbolAddress((void**)&Xs, g_Xs);
    cudaGetSymbolAddress((void**)&Wqt, g_Wqt);
    cudaGetSymbolAddress((void**)&Wkt, g_Wkt);
    cudaGetSymbolAddress((void**)&Qs, g_Qs);
    cudaGetSymbolAddress((void**)&Ks, g_Ks);
    cudaGetSymbolAddress((void**)&Ss, g_Ss);
    cudaGetSymbolAddress((void**)&Xt, g_Xt);

    cudaFuncSetAttribute(gemm_split<6, 3>, cudaFuncAttributeMaxDynamicSharedMemorySize, GEMM_SMEM);
    cudaFuncSetAttribute(gemm_split<4, 3>, cudaFuncAttributeMaxDynamicSharedMemorySize, GEMM_SMEM);
    cudaFuncSetAttribute(gemm_split<3, 2>, cudaFuncAttributeMaxDynamicSharedMemorySize, GEMM_SMEM);

    // split inputs
    split_rows<3><<<(N_TOK * DIM / 4) / 256, 256>>>(X, Xs, DIM);
    splitT<3><<<dim3(DIM / 32, DIM / 32), dim3(32, 8)>>>(Wq, Wqt, DIM, DIM);
    splitT<3><<<dim3(DIM / 32, DIM / 32), dim3(32, 8)>>>(Wk, Wkt, DIM, DIM);

    // Q = X Wq ; K = X Wk   (M=4096, N=1024, K=1024) — 6 products (full accuracy)
    gemm_split<6, 3><<<dim3(DIM / 128, N_TOK / 128), 256, GEMM_SMEM>>>(Xs, Wqt, Q, DIM, DIM, DIM / 64, 1.0f);
    gemm_split<6, 3><<<dim3(DIM / 128, N_TOK / 128), 256, GEMM_SMEM>>>(Xs, Wkt, K, DIM, DIM, DIM / 64, 1.0f);

    // split Q, K
    split_rows<3><<<(N_TOK * DIM / 4) / 256, 256>>>(Q, Qs, DIM);
    split_rows<3><<<(N_TOK * DIM / 4) / 256, 256>>>(K, Ks, DIM);

    // S = (Q K^T) / 32   (M=N=4096, K=1024) — 4 products (hh,hm,mh,mm)
    gemm_split<4, 3><<<dim3(N_TOK / 128, N_TOK / 128), 256, GEMM_SMEM>>>(Qs, Ks, S, N_TOK, DIM, DIM / 64, 0.03125f);

    softmax_rows<<<N_TOK, 256>>>(S);

    // split S (2-way) and X^T (2-way)
    split_rows<2><<<((size_t)N_TOK * N_TOK / 4) / 256, 256>>>(S, Ss, N_TOK);
    splitT<2><<<dim3(DIM / 32, N_TOK / 32), dim3(32, 8)>>>(X, Xt, N_TOK, DIM);

    // O = S X   (M=4096, N=1024, K=4096) — 3 products
    gemm_split<3, 2><<<dim3(DIM / 128, N_TOK / 128), 256, GEMM_SMEM>>>(Ss, Xt, O, DIM, N_TOK, N_TOK / 64, 1.0f);
}

// round 5
// speedup vs baseline: 2.9746x; 1.3221x over previous
#include <cuda_runtime.h>
#include <cuda_fp16.h>
#include <math_constants.h>
#include <cstdint>

#define N_TOK 4096
#define DIM   1024

// ---------------- scratch (__device__ globals; allocation-free contract) ----
__device__ float  g_S [(size_t)N_TOK * N_TOK];            // raw scaled logits
__device__ __half g_Xs [(size_t)N_TOK * 2 * DIM];         // split2 of X    [4096, 2048]
__device__ __half g_Wqt[(size_t)DIM   * 2 * DIM];         // split2 of Wq^T [1024, 2048]
__device__ __half g_Wkt[(size_t)DIM   * 2 * DIM];         // split2 of Wk^T [1024, 2048]
__device__ __half g_Qs [(size_t)N_TOK * 2 * DIM];         // split2 of Q    [4096, 2048]
__device__ __half g_Ks [(size_t)N_TOK * 2 * DIM];         // split2 of K    [4096, 2048]
__device__ __half g_Ss [(size_t)N_TOK * 2 * N_TOK];       // split2 of P    [4096, 8192]
__device__ __half g_Xt [(size_t)DIM   * 2 * N_TOK];       // split2 of X^T  [1024, 8192]

// ---------------------------------------------------------------------------
// HMMA split-fp16 GEMM:  C = alpha * (Ah Bh^T + Ah Bl^T + Al Bh^T)
// A: [M, 2K] fp16 row-major (hi | lo).  B: [N, 2K] fp16 row-major (K-major).
// Block 128x128, BK=64, 8 warps (2x4), warp tile 64x32, mma.m16n8k16.
// smem rows: 64 fp16 (128B) padded to 144B stride -> conflict-free ldmatrix.
// 3 stages, one __syncthreads per chunk (slot (c+S-1)%S finished last iter).
// EPI=0: fp32 store with alpha.  EPI=1: fp16 2-split store (hi|lo halves).
// ---------------------------------------------------------------------------
#define ROW_B 144
#define TILE_BYTES (128 * ROW_B)
#define STAGE_BYTES (2 * TILE_BYTES)
#define STAGES 3
#define GEMM_SMEM (STAGES * STAGE_BYTES)    // 110592

__device__ __forceinline__ uint32_t smem_u32(const void* p) {
    uint32_t a;
    asm("{ .reg .u64 t; cvta.to.shared.u64 t, %1; cvt.u32.u64 %0, t; }" : "=r"(a) : "l"(p));
    return a;
}
__device__ __forceinline__ void cp16(uint32_t dst, const void* src) {
    asm volatile("cp.async.cg.shared.global [%0], [%1], 16;\n" :: "r"(dst), "l"(src));
}
__device__ __forceinline__ void ldm_x4(uint32_t* r, uint32_t addr) {
    asm volatile("ldmatrix.sync.aligned.m8n8.x4.shared.b16 {%0,%1,%2,%3}, [%4];"
                 : "=r"(r[0]), "=r"(r[1]), "=r"(r[2]), "=r"(r[3]) : "r"(addr));
}
__device__ __forceinline__ void mma16816(float* c, const uint32_t* a, const uint32_t* b) {
    asm volatile("mma.sync.aligned.m16n8k16.row.col.f32.f16.f16.f32 "
                 "{%0,%1,%2,%3}, {%4,%5,%6,%7}, {%8,%9}, {%0,%1,%2,%3};"
                 : "+f"(c[0]), "+f"(c[1]), "+f"(c[2]), "+f"(c[3])
                 : "r"(a[0]), "r"(a[1]), "r"(a[2]), "r"(a[3]), "r"(b[0]), "r"(b[1]));
}

template <int EPI>
__global__ __launch_bounds__(256, 2)
void gemm_split(const __half* __restrict__ A, const __half* __restrict__ B,
                void* __restrict__ Cv, int N, int K, int kchunks, float alpha)
{
    extern __shared__ char smem[];
    const uint32_t su = smem_u32(smem);
    const int tid = threadIdx.x;
    const int wid = tid >> 5;
    const int lane = tid & 31;
    const int warp_m = wid >> 2;
    const int warp_n = wid & 3;
    const int lda = 2 * K;

    // products: hh, hl, lh
    const int ta[3] = {0, 0, 1};
    const int tb[3] = {0, 1, 0};
    const int nch = 3 * kchunks;

    float acc[4][4][4];
#pragma unroll
    for (int i = 0; i < 4; i++)
#pragma unroll
        for (int j = 0; j < 4; j++)
#pragma unroll
            for (int t = 0; t < 4; t++) acc[i][j][t] = 0.0f;

    auto load_chunk = [&](int cc) {
        int p  = cc / kchunks;
        int kc = cc - p * kchunks;
        const __half* aB = A + (size_t)(blockIdx.y * 128) * lda + (size_t)ta[p] * K + kc * 64;
        const __half* bB = B + (size_t)(blockIdx.x * 128) * lda + (size_t)tb[p] * K + kc * 64;
        uint32_t sA = su + (cc % STAGES) * STAGE_BYTES;
        uint32_t sB = sA + TILE_BYTES;
#pragma unroll
        for (int i = 0; i < 4; i++) {
            int s = tid + i * 256, row = s >> 3, seg = s & 7;
            cp16(sA + row * ROW_B + seg * 16, aB + (size_t)row * lda + seg * 8);
        }
#pragma unroll
        for (int i = 0; i < 4; i++) {
            int s = tid + i * 256, row = s >> 3, seg = s & 7;
            cp16(sB + row * ROW_B + seg * 16, bB + (size_t)row * lda + seg * 8);
        }
        asm volatile("cp.async.commit_group;\n" ::: "memory");
    };

#pragma unroll
    for (int c = 0; c < STAGES - 1; c++)
        if (c < nch) load_chunk(c);

    const uint32_t a_off = (uint32_t)((warp_m * 64 + (lane & 15)) * ROW_B + (lane >> 4) * 16);
    const uint32_t b_off = (uint32_t)((warp_n * 32 + (lane & 7) + ((lane >> 4) & 1) * 8) * ROW_B
                                      + ((lane >> 3) & 1) * 16);

    for (int c = 0; c < nch; c++) {
        asm volatile("cp.async.wait_group %0;\n" :: "n"(STAGES - 2) : "memory");
        __syncthreads();

        uint32_t sA = su + (c % STAGES) * STAGE_BYTES;
        uint32_t sB = sA + TILE_BYTES;
#pragma unroll
        for (int p = 0; p < 4; p++) {
            uint32_t a[4][4], b[2][4];
#pragma unroll
            for (int mt = 0; mt < 4; mt++)
                ldm_x4(a[mt], sA + a_off + mt * 16 * ROW_B + p * 32);
#pragma unroll
            for (int np = 0; np < 2; np++)
                ldm_x4(b[np], sB + b_off + np * 16 * ROW_B + p * 32);
#pragma unroll
            for (int mt = 0; mt < 4; mt++)
#pragma unroll
                for (int nt = 0; nt < 4; nt++)
                    mma16816(acc[mt][nt], a[mt], &b[nt >> 1][(nt & 1) * 2]);
        }

        int cl = c + STAGES - 1;
        if (cl < nch) load_chunk(cl);
    }

    const int row0 = blockIdx.y * 128 + warp_m * 64 + (lane >> 2);
    const int col0 = blockIdx.x * 128 + warp_n * 32 + (lane & 3) * 2;

    if (EPI == 0) {
        float* C = (float*)Cv;
#pragma unroll
        for (int mt = 0; mt < 4; mt++) {
#pragma unroll
            for (int nt = 0; nt < 4; nt++) {
                float2 v0 = make_float2(alpha * acc[mt][nt][0], alpha * acc[mt][nt][1]);
                float2 v1 = make_float2(alpha * acc[mt][nt][2], alpha * acc[mt][nt][3]);
                size_t r0 = (size_t)(row0 + mt * 16) * N + col0 + nt * 8;
                *reinterpret_cast<float2*>(&C[r0])                 = v0;
                *reinterpret_cast<float2*>(&C[r0 + (size_t)8 * N]) = v1;
            }
        }
    } else {
        // fp16 2-split store: Cs[row][col] = hi, Cs[row][N + col] = lo; row stride 2N
        __half* Cs = (__half*)Cv;
#pragma unroll
        for (int mt = 0; mt < 4; mt++) {
#pragma unroll
            for (int nt = 0; nt < 4; nt++) {
#pragma unroll
                for (int half_row = 0; half_row < 2; half_row++) {
                    float v0 = acc[mt][nt][half_row * 2 + 0];
                    float v1 = acc[mt][nt][half_row * 2 + 1];
                    __half h0 = __float2half_rn(v0);
                    __half h1 = __float2half_rn(v1);
                    __half l0 = __float2half_rn(v0 - __half2float(h0));
                    __half l1 = __float2half_rn(v1 - __half2float(h1));
                    size_t base = (size_t)(row0 + mt * 16 + half_row * 8) * (2 * N) + col0 + nt * 8;
                    __half2 hh; hh.x = h0; hh.y = h1;
                    __half2 ll; ll.x = l0; ll.y = l1;
                    *reinterpret_cast<__half2*>(&Cs[base])     = hh;
                    *reinterpret_cast<__half2*>(&Cs[base + N]) = ll;
                }
            }
        }
    }
}

// ---------------------------------------------------------------------------
// split X rows: fp32 [R, C] -> fp16 [R, 2C] (hi | lo)
// ---------------------------------------------------------------------------
__global__ __launch_bounds__(256)
void split_rows_h(const float* __restrict__ in, __half* __restrict__ out, int C)
{
    size_t idx = (size_t)blockIdx.x * blockDim.x + threadIdx.x;   // one float4
    int cq = C >> 2;
    size_t r = idx / cq;
    int c4 = (int)(idx - r * cq);
    float4 v = reinterpret_cast<const float4*>(in)[idx];
    float x[4] = {v.x, v.y, v.z, v.w};
    __half h[4], l[4];
#pragma unroll
    for (int i = 0; i < 4; i++) {
        h[i] = __float2half_rn(x[i]);
        l[i] = __float2half_rn(x[i] - __half2float(h[i]));
    }
    __half* o = out + r * (size_t)(2 * C) + c4 * 4;
    __half2 p0, p1;
    p0.x = h[0]; p0.y = h[1]; p1.x = h[2]; p1.y = h[3];
    *reinterpret_cast<__half2*>(o)     = p0;
    *reinterpret_cast<__half2*>(o + 2) = p1;
    p0.x = l[0]; p0.y = l[1]; p1.x = l[2]; p1.y = l[3];
    *reinterpret_cast<__half2*>(o + C)     = p0;
    *reinterpret_cast<__half2*>(o + C + 2) = p1;
}

// in [K,N] fp32 -> out [N, 2K] fp16 (transpose + split)
__global__ __launch_bounds__(256)
void splitT_h(const float* __restrict__ in, __half* __restrict__ out, int K, int N)
{
    __shared__ float tile[32][33];
    int k0 = blockIdx.y * 32, n0 = blockIdx.x * 32;
    int tx = threadIdx.x, ty = threadIdx.y;   // (32, 8)
#pragma unroll
    for (int j = 0; j < 4; j++)
        tile[ty + j * 8][tx] = in[(size_t)(k0 + ty + j * 8) * N + n0 + tx];
    __syncthreads();
#pragma unroll
    for (int j = 0; j < 4; j++) {
        int n = n0 + ty + j * 8, k = k0 + tx;
        float x = tile[tx][ty + j * 8];
        __half h = __float2half_rn(x);
        __half l = __float2half_rn(x - __half2float(h));
        __half* o = out + (size_t)n * (2 * K) + k;
        o[0] = h;
        o[K] = l;
    }
}

// ---------------------------------------------------------------------------
// Row softmax reading fp32 logits, writing fp16 2-split probabilities
// ---------------------------------------------------------------------------
__global__ __launch_bounds__(256)
void softmax_split(const float* __restrict__ S, __half* __restrict__ Ss)
{
    const int row = blockIdx.x;
    const float* r = S + (size_t)row * N_TOK;
    __half* o = Ss + (size_t)row * (2 * N_TOK);
    const int tid = threadIdx.x;

    float v[16];
    float m = -CUDART_INF_F;
#pragma unroll
    for (int i = 0; i < 16; i++) { v[i] = r[tid + i * 256]; m = fmaxf(m, v[i]); }

    __shared__ float red[8];
#pragma unroll
    for (int off = 16; off > 0; off >>= 1) m = fmaxf(m, __shfl_xor_sync(0xffffffffu, m, off));
    if ((tid & 31) == 0) red[tid >> 5] = m;
    __syncthreads();
    m = red[0];
#pragma unroll
    for (int w = 1; w < 8; w++) m = fmaxf(m, red[w]);

    float sum = 0.0f;
#pragma unroll
    for (int i = 0; i < 16; i++) { v[i] = expf(v[i] - m); sum += v[i]; }
    __syncthreads();
#pragma unroll
    for (int off = 16; off > 0; off >>= 1) sum += __shfl_xor_sync(0xffffffffu, sum, off);
    if ((tid & 31) == 0) red[tid >> 5] = sum;
    __syncthreads();
    sum = 0.0f;
#pragma unroll
    for (int w = 0; w < 8; w++) sum += red[w];

    const float inv = 1.0f / sum;
#pragma unroll
    for (int i = 0; i < 16; i++) {
        float p = v[i] * inv;
        __half h = __float2half_rn(p);
        __half l = __float2half_rn(p - __half2float(h));
        o[tid + i * 256]         = h;
        o[N_TOK + tid + i * 256] = l;
    }
}

// ---------------------------------------------------------------------------
extern "C" void kernel_launch(void* const* d_in, const int* in_sizes, int n_in,
                              void* d_out, int out_size)
{
    const float* X  = (const float*)d_in[0];
    const float* Wq = (const float*)d_in[1];
    const float* Wk = (const float*)d_in[2];
    float* O = (float*)d_out;

    float* S;
    __half *Xs, *Wqt, *Wkt, *Qs, *Ks, *Ss, *Xt;
    cudaGetSymbolAddress((void**)&S,  g_S);
    cudaGetSymbolAddress((void**)&Xs, g_Xs);
    cudaGetSymbolAddress((void**)&Wqt, g_Wqt);
    cudaGetSymbolAddress((void**)&Wkt, g_Wkt);
    cudaGetSymbolAddress((void**)&Qs, g_Qs);
    cudaGetSymbolAddress((void**)&Ks, g_Ks);
    cudaGetSymbolAddress((void**)&Ss, g_Ss);
    cudaGetSymbolAddress((void**)&Xt, g_Xt);

    cudaFuncSetAttribute(gemm_split<0>, cudaFuncAttributeMaxDynamicSharedMemorySize, GEMM_SMEM);
    cudaFuncSetAttribute(gemm_split<1>, cudaFuncAttributeMaxDynamicSharedMemorySize, GEMM_SMEM);

    // pre-splits
    split_rows_h<<<(N_TOK * DIM / 4) / 256, 256>>>(X, Xs, DIM);
    splitT_h<<<dim3(DIM / 32, DIM / 32), dim3(32, 8)>>>(Wq, Wqt, DIM, DIM);
    splitT_h<<<dim3(DIM / 32, DIM / 32), dim3(32, 8)>>>(Wk, Wkt, DIM, DIM);
    splitT_h<<<dim3(DIM / 32, N_TOK / 32), dim3(32, 8)>>>(X, Xt, N_TOK, DIM);

    // Q = X Wq ; K = X Wk  (epilogue writes fp16 2-split directly)
    gemm_split<1><<<dim3(DIM / 128, N_TOK / 128), 256, GEMM_SMEM>>>(Xs, Wqt, Qs, DIM, DIM, DIM / 64, 1.0f);
    gemm_split<1><<<dim3(DIM / 128, N_TOK / 128), 256, GEMM_SMEM>>>(Xs, Wkt, Ks, DIM, DIM, DIM / 64, 1.0f);

    // S = (Q K^T) / 32
    gemm_split<0><<<dim3(N_TOK / 128, N_TOK / 128), 256, GEMM_SMEM>>>(Qs, Ks, S, N_TOK, DIM, DIM / 64, 0.03125f);

    // P = softmax(S), written as fp16 2-split
    softmax_split<<<N_TOK, 256>>>(S, Ss);

    // O = P X
    gemm_split<0><<<dim3(DIM / 128, N_TOK / 128), 256, GEMM_SMEM>>>(Ss, Xt, O, DIM, N_TOK, N_TOK / 64, 1.0f);
}

// round 6
// speedup vs baseline: 3.5432x; 1.1912x over previous
#include <cuda_runtime.h>
#include <cuda_fp16.h>
#include <math_constants.h>
#include <cstdint>

#define N_TOK 4096
#define DIM   1024

// ---------------- scratch (__device__ globals; allocation-free contract) ----
__device__ float  g_S [(size_t)N_TOK * N_TOK];            // raw scaled logits
__device__ __half g_Xs [(size_t)N_TOK * 2 * DIM];         // split2 of X    [4096, 2048]
__device__ __half g_Wqt[(size_t)DIM   * 2 * DIM];         // split2 of Wq^T [1024, 2048]
__device__ __half g_Wkt[(size_t)DIM   * 2 * DIM];         // split2 of Wk^T [1024, 2048]
__device__ __half g_Qs [(size_t)N_TOK * 2 * DIM];         // split2 of Q    [4096, 2048]
__device__ __half g_Ks [(size_t)N_TOK * 2 * DIM];         // split2 of K    [4096, 2048]
__device__ __half g_P  [(size_t)N_TOK * N_TOK];           // P fp16 (hi only) [4096, 4096]
__device__ __half g_Xt [(size_t)DIM   * N_TOK];           // X^T fp16 (hi only) [1024, 4096]

// ---------------------------------------------------------------------------
// HMMA split-fp16 GEMM:  C = alpha * sum_{p<NPROD} A_split[ta[p]] @ B_split[tb[p]]^T
// A: [M, SPLITS*K] fp16 row-major.  B: [N, SPLITS*K] fp16 row-major (K-major).
// Block 128x128, BK=64, 8 warps (2x4), warp tile 64x32, mma.m16n8k16.
// smem rows: 64 fp16 (128B) padded to 144B stride -> conflict-free ldmatrix.
// 3 stages, one __syncthreads per chunk; loads issued right after the barrier
// (slot (c+S-1)%S == (c-1)%S was last read in iter c-1, protected by barrier).
// Empty commit_group on tail iters keeps wait_group counting sound.
// EPI=0: fp32 store with alpha.  EPI=1: fp16 2-split store (hi|lo halves).
// ---------------------------------------------------------------------------
#define ROW_B 144
#define TILE_BYTES (128 * ROW_B)
#define STAGE_BYTES (2 * TILE_BYTES)
#define STAGES 3
#define GEMM_SMEM (STAGES * STAGE_BYTES)    // 110592

__device__ __forceinline__ uint32_t smem_u32(const void* p) {
    uint32_t a;
    asm("{ .reg .u64 t; cvta.to.shared.u64 t, %1; cvt.u32.u64 %0, t; }" : "=r"(a) : "l"(p));
    return a;
}
__device__ __forceinline__ void cp16(uint32_t dst, const void* src) {
    asm volatile("cp.async.cg.shared.global [%0], [%1], 16;\n" :: "r"(dst), "l"(src));
}
__device__ __forceinline__ void ldm_x4(uint32_t* r, uint32_t addr) {
    asm volatile("ldmatrix.sync.aligned.m8n8.x4.shared.b16 {%0,%1,%2,%3}, [%4];"
                 : "=r"(r[0]), "=r"(r[1]), "=r"(r[2]), "=r"(r[3]) : "r"(addr));
}
__device__ __forceinline__ void mma16816(float* c, const uint32_t* a, const uint32_t* b) {
    asm volatile("mma.sync.aligned.m16n8k16.row.col.f32.f16.f16.f32 "
                 "{%0,%1,%2,%3}, {%4,%5,%6,%7}, {%8,%9}, {%0,%1,%2,%3};"
                 : "+f"(c[0]), "+f"(c[1]), "+f"(c[2]), "+f"(c[3])
                 : "r"(a[0]), "r"(a[1]), "r"(a[2]), "r"(a[3]), "r"(b[0]), "r"(b[1]));
}

template <int EPI, int NPROD, int SPLITS>
__global__ __launch_bounds__(256, 2)
void gemm_split(const __half* __restrict__ A, const __half* __restrict__ B,
                void* __restrict__ Cv, int N, int K, int kchunks, float alpha)
{
    extern __shared__ char smem[];
    const uint32_t su = smem_u32(smem);
    const int tid = threadIdx.x;
    const int wid = tid >> 5;
    const int lane = tid & 31;
    const int warp_m = wid >> 2;
    const int warp_n = wid & 3;
    const int lda = SPLITS * K;

    // products: hh, hl, lh (prefix works for NPROD=1)
    const int ta[3] = {0, 0, 1};
    const int tb[3] = {0, 1, 0};
    const int nch = NPROD * kchunks;

    float acc[4][4][4];
#pragma unroll
    for (int i = 0; i < 4; i++)
#pragma unroll
        for (int j = 0; j < 4; j++)
#pragma unroll
            for (int t = 0; t < 4; t++) acc[i][j][t] = 0.0f;

    auto load_chunk = [&](int cc) {
        int p  = cc / kchunks;
        int kc = cc - p * kchunks;
        const __half* aB = A + (size_t)(blockIdx.y * 128) * lda + (size_t)ta[p] * K + kc * 64;
        const __half* bB = B + (size_t)(blockIdx.x * 128) * lda + (size_t)tb[p] * K + kc * 64;
        uint32_t sA = su + (cc % STAGES) * STAGE_BYTES;
        uint32_t sB = sA + TILE_BYTES;
#pragma unroll
        for (int i = 0; i < 4; i++) {
            int s = tid + i * 256, row = s >> 3, seg = s & 7;
            cp16(sA + row * ROW_B + seg * 16, aB + (size_t)row * lda + seg * 8);
        }
#pragma unroll
        for (int i = 0; i < 4; i++) {
            int s = tid + i * 256, row = s >> 3, seg = s & 7;
            cp16(sB + row * ROW_B + seg * 16, bB + (size_t)row * lda + seg * 8);
        }
        asm volatile("cp.async.commit_group;\n" ::: "memory");
    };

#pragma unroll
    for (int c = 0; c < STAGES - 1; c++)
        if (c < nch) load_chunk(c);
        else asm volatile("cp.async.commit_group;\n" ::: "memory");

    const uint32_t a_off = (uint32_t)((warp_m * 64 + (lane & 15)) * ROW_B + (lane >> 4) * 16);
    const uint32_t b_off = (uint32_t)((warp_n * 32 + (lane & 7) + ((lane >> 4) & 1) * 8) * ROW_B
                                      + ((lane >> 3) & 1) * 16);

    for (int c = 0; c < nch; c++) {
        asm volatile("cp.async.wait_group %0;\n" :: "n"(STAGES - 2) : "memory");
        __syncthreads();

        // issue next loads BEFORE compute: target slot was last read in iter c-1
        int cl = c + STAGES - 1;
        if (cl < nch) load_chunk(cl);
        else asm volatile("cp.async.commit_group;\n" ::: "memory");

        uint32_t sA = su + (c % STAGES) * STAGE_BYTES;
        uint32_t sB = sA + TILE_BYTES;
#pragma unroll
        for (int p = 0; p < 4; p++) {
            uint32_t a[4][4], b[2][4];
#pragma unroll
            for (int mt = 0; mt < 4; mt++)
                ldm_x4(a[mt], sA + a_off + mt * 16 * ROW_B + p * 32);
#pragma unroll
            for (int np = 0; np < 2; np++)
                ldm_x4(b[np], sB + b_off + np * 16 * ROW_B + p * 32);
#pragma unroll
            for (int mt = 0; mt < 4; mt++)
#pragma unroll
                for (int nt = 0; nt < 4; nt++)
                    mma16816(acc[mt][nt], a[mt], &b[nt >> 1][(nt & 1) * 2]);
        }
    }

    const int row0 = blockIdx.y * 128 + warp_m * 64 + (lane >> 2);
    const int col0 = blockIdx.x * 128 + warp_n * 32 + (lane & 3) * 2;

    if (EPI == 0) {
        float* C = (float*)Cv;
#pragma unroll
        for (int mt = 0; mt < 4; mt++) {
#pragma unroll
            for (int nt = 0; nt < 4; nt++) {
                float2 v0 = make_float2(alpha * acc[mt][nt][0], alpha * acc[mt][nt][1]);
                float2 v1 = make_float2(alpha * acc[mt][nt][2], alpha * acc[mt][nt][3]);
                size_t r0 = (size_t)(row0 + mt * 16) * N + col0 + nt * 8;
                *reinterpret_cast<float2*>(&C[r0])                 = v0;
                *reinterpret_cast<float2*>(&C[r0 + (size_t)8 * N]) = v1;
            }
        }
    } else {
        // fp16 2-split store: Cs[row][col] = hi, Cs[row][N + col] = lo; row stride 2N
        __half* Cs = (__half*)Cv;
#pragma unroll
        for (int mt = 0; mt < 4; mt++) {
#pragma unroll
            for (int nt = 0; nt < 4; nt++) {
#pragma unroll
                for (int hr = 0; hr < 2; hr++) {
                    float v0 = acc[mt][nt][hr * 2 + 0];
                    float v1 = acc[mt][nt][hr * 2 + 1];
                    __half h0 = __float2half_rn(v0);
                    __half h1 = __float2half_rn(v1);
                    __half l0 = __float2half_rn(v0 - __half2float(h0));
                    __half l1 = __float2half_rn(v1 - __half2float(h1));
                    size_t base = (size_t)(row0 + mt * 16 + hr * 8) * (2 * N) + col0 + nt * 8;
                    __half2 hh; hh.x = h0; hh.y = h1;
                    __half2 ll; ll.x = l0; ll.y = l1;
                    *reinterpret_cast<__half2*>(&Cs[base])     = hh;
                    *reinterpret_cast<__half2*>(&Cs[base + N]) = ll;
                }
            }
        }
    }
}

// ---------------------------------------------------------------------------
// split X rows: fp32 [R, C] -> fp16 [R, 2C] (hi | lo)
// ---------------------------------------------------------------------------
__global__ __launch_bounds__(256)
void split_rows_h(const float* __restrict__ in, __half* __restrict__ out, int C)
{
    size_t idx = (size_t)blockIdx.x * blockDim.x + threadIdx.x;   // one float4
    int cq = C >> 2;
    size_t r = idx / cq;
    int c4 = (int)(idx - r * cq);
    float4 v = reinterpret_cast<const float4*>(in)[idx];
    float x[4] = {v.x, v.y, v.z, v.w};
    __half h[4], l[4];
#pragma unroll
    for (int i = 0; i < 4; i++) {
        h[i] = __float2half_rn(x[i]);
        l[i] = __float2half_rn(x[i] - __half2float(h[i]));
    }
    __half* o = out + r * (size_t)(2 * C) + c4 * 4;
    __half2 p0, p1;
    p0.x = h[0]; p0.y = h[1]; p1.x = h[2]; p1.y = h[3];
    *reinterpret_cast<__half2*>(o)     = p0;
    *reinterpret_cast<__half2*>(o + 2) = p1;
    p0.x = l[0]; p0.y = l[1]; p1.x = l[2]; p1.y = l[3];
    *reinterpret_cast<__half2*>(o + C)     = p0;
    *reinterpret_cast<__half2*>(o + C + 2) = p1;
}

// in [K,N] fp32 -> out [N, S*K] fp16 (transpose; S=2: hi|lo, S=1: hi only)
template <int S>
__global__ __launch_bounds__(256)
void splitT_h(const float* __restrict__ in, __half* __restrict__ out, int K, int N)
{
    __shared__ float tile[32][33];
    int k0 = blockIdx.y * 32, n0 = blockIdx.x * 32;
    int tx = threadIdx.x, ty = threadIdx.y;   // (32, 8)
#pragma unroll
    for (int j = 0; j < 4; j++)
        tile[ty + j * 8][tx] = in[(size_t)(k0 + ty + j * 8) * N + n0 + tx];
    __syncthreads();
#pragma unroll
    for (int j = 0; j < 4; j++) {
        int n = n0 + ty + j * 8, k = k0 + tx;
        float x = tile[tx][ty + j * 8];
        __half h = __float2half_rn(x);
        __half* o = out + (size_t)n * (S * K) + k;
        o[0] = h;
        if (S == 2) o[K] = __float2half_rn(x - __half2float(h));
    }
}

// ---------------------------------------------------------------------------
// Row softmax reading fp32 logits, writing plain fp16 probabilities
// ---------------------------------------------------------------------------
__global__ __launch_bounds__(256)
void softmax_h(const float* __restrict__ S, __half* __restrict__ P)
{
    const int row = blockIdx.x;
    const float* r = S + (size_t)row * N_TOK;
    __half* o = P + (size_t)row * N_TOK;
    const int tid = threadIdx.x;

    float v[16];
    float m = -CUDART_INF_F;
#pragma unroll
    for (int i = 0; i < 16; i++) { v[i] = r[tid + i * 256]; m = fmaxf(m, v[i]); }

    __shared__ float red[8];
#pragma unroll
    for (int off = 16; off > 0; off >>= 1) m = fmaxf(m, __shfl_xor_sync(0xffffffffu, m, off));
    if ((tid & 31) == 0) red[tid >> 5] = m;
    __syncthreads();
    m = red[0];
#pragma unroll
    for (int w = 1; w < 8; w++) m = fmaxf(m, red[w]);

    float sum = 0.0f;
#pragma unroll
    for (int i = 0; i < 16; i++) { v[i] = expf(v[i] - m); sum += v[i]; }
    __syncthreads();
#pragma unroll
    for (int off = 16; off > 0; off >>= 1) sum += __shfl_xor_sync(0xffffffffu, sum, off);
    if ((tid & 31) == 0) red[tid >> 5] = sum;
    __syncthreads();
    sum = 0.0f;
#pragma unroll
    for (int w = 0; w < 8; w++) sum += red[w];

    const float inv = 1.0f / sum;
#pragma unroll
    for (int i = 0; i < 8; i++) {
        __half2 p2;
        p2.x = __float2half_rn(v[2 * i]     * inv);
        p2.y = __float2half_rn(v[2 * i + 1] * inv);
        // v[2i], v[2i+1] are at columns tid+2i*256 and tid+(2i+1)*256 (not adjacent)
        o[tid + (2 * i) * 256]     = p2.x;
        o[tid + (2 * i + 1) * 256] = p2.y;
    }
}

// ---------------------------------------------------------------------------
extern "C" void kernel_launch(void* const* d_in, const int* in_sizes, int n_in,
                              void* d_out, int out_size)
{
    const float* X  = (const float*)d_in[0];
    const float* Wq = (const float*)d_in[1];
    const float* Wk = (const float*)d_in[2];
    float* O = (float*)d_out;

    float* S;
    __half *Xs, *Wqt, *Wkt, *Qs, *Ks, *P, *Xt;
    cudaGetSymbolAddress((void**)&S,  g_S);
    cudaGetSymbolAddress((void**)&Xs, g_Xs);
    cudaGetSymbolAddress((void**)&Wqt, g_Wqt);
    cudaGetSymbolAddress((void**)&Wkt, g_Wkt);
    cudaGetSymbolAddress((void**)&Qs, g_Qs);
    cudaGetSymbolAddress((void**)&Ks, g_Ks);
    cudaGetSymbolAddress((void**)&P,  g_P);
    cudaGetSymbolAddress((void**)&Xt, g_Xt);

    cudaFuncSetAttribute(gemm_split<1, 3, 2>, cudaFuncAttributeMaxDynamicSharedMemorySize, GEMM_SMEM);
    cudaFuncSetAttribute(gemm_split<0, 3, 2>, cudaFuncAttributeMaxDynamicSharedMemorySize, GEMM_SMEM);
    cudaFuncSetAttribute(gemm_split<0, 1, 1>, cudaFuncAttributeMaxDynamicSharedMemorySize, GEMM_SMEM);

    // pre-splits
    split_rows_h<<<(N_TOK * DIM / 4) / 256, 256>>>(X, Xs, DIM);
    splitT_h<2><<<dim3(DIM / 32, DIM / 32), dim3(32, 8)>>>(Wq, Wqt, DIM, DIM);
    splitT_h<2><<<dim3(DIM / 32, DIM / 32), dim3(32, 8)>>>(Wk, Wkt, DIM, DIM);
    splitT_h<1><<<dim3(DIM / 32, N_TOK / 32), dim3(32, 8)>>>(X, Xt, N_TOK, DIM);

    // Q = X Wq ; K = X Wk  (3 products, epilogue writes fp16 2-split)
    gemm_split<1, 3, 2><<<dim3(DIM / 128, N_TOK / 128), 256, GEMM_SMEM>>>(Xs, Wqt, Qs, DIM, DIM, DIM / 64, 1.0f);
    gemm_split<1, 3, 2><<<dim3(DIM / 128, N_TOK / 128), 256, GEMM_SMEM>>>(Xs, Wkt, Ks, DIM, DIM, DIM / 64, 1.0f);

    // S = (Q K^T) / 32  (3 products)
    gemm_split<0, 3, 2><<<dim3(N_TOK / 128, N_TOK / 128), 256, GEMM_SMEM>>>(Qs, Ks, S, N_TOK, DIM, DIM / 64, 0.03125f);

    // P = softmax(S), plain fp16
    softmax_h<<<N_TOK, 256>>>(S, P);

    // O = P X  (single product: Ph @ Xh^T)
    gemm_split<0, 1, 1><<<dim3(DIM / 128, N_TOK / 128), 256, GEMM_SMEM>>>(P, Xt, O, DIM, N_TOK, N_TOK / 64, 1.0f);
}